// round 14
// baseline (speedup 1.0000x reference)
#include <cuda_runtime.h>
#include <cuda_fp16.h>
#include <math.h>
#include <stdint.h>

// ============================================================================
// GroupLorentzConv2d, fp16 m16n8k16 tensor-core path (sm_80 PTX on B200 HMMA).
//
//   C[p, n] = sum_d A[p,d] * W[n,d] + t(p)*wti[(n&63)+1],  n = g*64 + o
//   Flat-index pairing (as the reference einsum):
//     A side: d = kp*64 + cp  -> x[b, h+dy(kp), w+dx(kp), 1+cp]
//     W side: d = cw*9  + kw  -> rot90^g(weight_space[o, cw])[kw]
//   K = 576 = 9 chunks x 64 (one 3x3 tap per chunk)
//   out[b,g,h,w,0]   = sqrt(1 + sum_o C[p, g*64+o]^2)
//   out[b,g,h,w,1+o] = C[p, g*64+o]
//
// CTA: 128 pixels x 128 outputs, 8 warps (32x64 warp tile), 2 CTAs/SM.
// A is RESIDENT in smem [5 rows][66 px][64ch]. PROLOGUE SLIMMED (R12 regression
// fix): only the 74 border slots are zeroed (OOB rows are redirected to row 4
// by the per-chunk rowslot select and never read), the fill is branchless with
// clamped rows and 2-row load batching (4x MLP), and the zero-phase barrier is
// gone (zeroed and filled slots are disjoint). B: 3-stage cp.async ring.
// ============================================================================

typedef uint32_t u32;

__device__ __align__(16) __half g_Wt[9 * 256 * 64];   // [tap][n][cp]
__device__ float g_tmap[16 * 64 * 64];

// ---------------- prep kernel: tmap + weights only ---------------------------
// blocks [0,256): tmap | [256,832): weights
__global__ void prep_all(const float* __restrict__ x,
                         const float* __restrict__ ws) {
    int blk = blockIdx.x;
    if (blk < 256) {
        int i = blk * 256 + threadIdx.x;
        int w = i & 63, h = (i >> 6) & 63, b = i >> 12;
        float s = 0.f;
        #pragma unroll
        for (int dy = -1; dy <= 1; dy++) {
            int hh = h + dy;
            #pragma unroll
            for (int dx = -1; dx <= 1; dx++) {
                int ww = w + dx;
                float v = 0.f;
                if (hh >= 0 && hh < 64 && ww >= 0 && ww < 64)
                    v = x[((size_t)(b * 64 + hh) * 64 + ww) * 65];
                v = fmaxf(v, 1.0f);
                s = fmaf(v, v, s);
            }
        }
        g_tmap[i] = sqrtf(s - 8.0f);
        return;
    }
    {
        int i = (blk - 256) * 256 + threadIdx.x;   // [tap][n][cp]
        if (i >= 9 * 256 * 64) return;
        int kc = i & 63;                 // cp (k within chunk)
        int n  = (i >> 6) & 255;
        int kp = i >> 14;                // tap
        int g = n >> 6, o = n & 63;
        int d  = kp * 64 + kc;           // flat index, tap-major (A side)
        int cw = d / 9, kw = d - cw * 9; // same d, channel-major (W side)
        int r = kw / 3, cc = kw - r * 3;
        int i2, j2;
        switch (g) {              // numpy rot90^g (CCW): rot90(A)[i,j] = A[j, 2-i]
            case 0:  i2 = r;      j2 = cc;     break;
            case 1:  i2 = cc;     j2 = 2 - r;  break;
            case 2:  i2 = 2 - r;  j2 = 2 - cc; break;
            default: i2 = 2 - cc; j2 = r;      break;
        }
        g_Wt[i] = __float2half_rn(ws[(o * 64 + cw) * 9 + i2 * 3 + j2]);
    }
}

// ---------------- main kernel ------------------------------------------------
// smem: A-resident [5 rows][66 px][128 B]      @0      (42,240 B)
//       B ring: 3 stages x [128 n][64 k]f16    @43008  (3 x 16,384 B)
//       stage float[2][128][65]                @0      (66,560 B, aliases, post-loop)
#define SM_AR 0
#define SM_B  43008
#define SMEM_BYTES (43008 + 49152)

__device__ __forceinline__ void cp16(u32 dst, const void* src, int sz) {
    asm volatile("cp.async.cg.shared.global [%0], [%1], 16, %2;"
                 :: "r"(dst), "l"(src), "r"(sz));
}
__device__ __forceinline__ void ldm4(u32* r, u32 addr) {
    asm volatile("ldmatrix.sync.aligned.m8n8.x4.shared.b16 {%0,%1,%2,%3}, [%4];"
                 : "=r"(r[0]), "=r"(r[1]), "=r"(r[2]), "=r"(r[3]) : "r"(addr));
}
__device__ __forceinline__ void mma16(float* c, const u32* a, const u32* b) {
    asm volatile(
        "mma.sync.aligned.m16n8k16.row.col.f32.f16.f16.f32 "
        "{%0,%1,%2,%3}, {%4,%5,%6,%7}, {%8,%9}, {%0,%1,%2,%3};"
        : "+f"(c[0]), "+f"(c[1]), "+f"(c[2]), "+f"(c[3])
        : "r"(a[0]), "r"(a[1]), "r"(a[2]), "r"(a[3]), "r"(b[0]), "r"(b[1]));
}

__global__ void __launch_bounds__(256, 2) lorentz_mma_kernel(
    const float* __restrict__ x,     // (16,64,64,65)
    const float* __restrict__ wti,   // (65,1)
    float* __restrict__ out)         // (16,4,64,64,65)
{
    extern __shared__ __align__(16) char sm[];
    const int tid  = threadIdx.x;
    const int lane = tid & 31, wid = tid >> 5;
    const int wm = wid & 3;          // pixel-warp 0..3  (32 px each)
    const int wn = wid >> 2;         // out-warp 0..1    (64 out each = one g)
    const int bid = blockIdx.x;
    const int nh  = bid & 1;         // n-half: outputs [nh*128, nh*128+128)
    const int mt_ = bid >> 1;
    const int b   = mt_ >> 5;
    const int h0  = (mt_ & 31) << 1; // rows h0, h0+1

    const u32 smb = (u32)__cvta_generic_to_shared(sm);

    // ---- B loader: 3-stage cp.async ring (XOR-swizzled) ----
    auto loadB = [&](int kp, int s) {
        const __half* base = g_Wt + ((size_t)kp * 256 + nh * 128) * 64;
        #pragma unroll
        for (int it = 0; it < 4; it++) {
            int idx = tid + it * 256;        // 128 n x 8 vec
            int n = idx >> 3, v = idx & 7;
            cp16(smb + SM_B + s * 16384 + n * 128 + ((v ^ (n & 7)) << 4),
                 base + idx * 8, 16);
        }
    };

    loadB(0, 0);
    asm volatile("cp.async.commit_group;");
    loadB(1, 1);
    asm volatile("cp.async.commit_group;");

    // ---- border-only zeroing: row 4 (66 slots) + cols 0/65 of rows 0-3 -----
    // (OOB rows are redirected to row 4 by rowslot select; interior slots are
    //  fully overwritten by the fill below — disjoint, so no barrier needed.)
    {
        float4 z = make_float4(0.f, 0.f, 0.f, 0.f);
        for (int i = tid; i < 592; i += 256) {       // 74 slots x 8 float4
            int s = i >> 3, v = i & 7;
            int slot;
            if (s < 66) slot = 4 * 66 + s;
            else { int t = s - 66; slot = (t >> 1) * 66 + ((t & 1) ? 65 : 0); }
            *(float4*)(sm + SM_AR + slot * 128 + v * 16) = z;
        }
    }

    // ---- accumulator init first: overlap tmap/wti LDG latency with fill ----
    float tv[2][2];
    #pragma unroll
    for (int mt = 0; mt < 2; mt++)
        #pragma unroll
        for (int rr = 0; rr < 2; rr++) {
            int p = wm * 32 + mt * 16 + rr * 8 + (lane >> 2);
            tv[mt][rr] = g_tmap[(size_t)(b * 64 + h0 + (p >> 6)) * 64 + (p & 63)];
        }
    float acc[2][8][4];
    #pragma unroll
    for (int nt = 0; nt < 8; nt++) {
        float w0 = wti[1 + nt * 8 + 2 * (lane & 3)];
        float w1 = wti[2 + nt * 8 + 2 * (lane & 3)];
        #pragma unroll
        for (int mt = 0; mt < 2; mt++) {
            acc[mt][nt][0] = tv[mt][0] * w0;
            acc[mt][nt][1] = tv[mt][0] * w1;
            acc[mt][nt][2] = tv[mt][1] * w0;
            acc[mt][nt][3] = tv[mt][1] * w1;
        }
    }

    // ---- A-resident fill: branchless (clamped rows), 2-row load batches ----
    {
        const int px = tid & 63;         // pixel w
        const int q  = tid >> 6;         // channel quarter: ch 16q..16q+15
        #pragma unroll
        for (int rp = 0; rp < 2; rp++) {
            float v[2][16];
            #pragma unroll
            for (int rr = 0; rr < 2; rr++) {
                int hh = h0 - 1 + rp * 2 + rr;
                int hc = hh < 0 ? 0 : (hh > 63 ? 63 : hh);   // clamped; OOB rows
                const float* srcp = x +                       // are never read
                    ((size_t)(b * 64 + hc) * 64 + px) * 65 + 1 + q * 16;
                #pragma unroll
                for (int j = 0; j < 16; j++) v[rr][j] = srcp[j];
            }
            #pragma unroll
            for (int rr = 0; rr < 2; rr++) {
                __half2 h2[8];
                #pragma unroll
                for (int j = 0; j < 8; j++)
                    h2[j] = __floats2half2_rn(v[rr][2 * j], v[rr][2 * j + 1]);
                int slot = (rp * 2 + rr) * 66 + px + 1;
                char* dstp = sm + SM_AR + slot * 128;
                int v0 = q * 2, v1 = v0 + 1;
                *(uint4*)(dstp + ((v0 ^ (slot & 7)) << 4)) = *(uint4*)&h2[0];
                *(uint4*)(dstp + ((v1 ^ (slot & 7)) << 4)) = *(uint4*)&h2[4];
            }
        }
    }

    // ---- main loop: 9 tap-chunks (k=64), FULLY UNROLLED ---------------------
    const int grp = lane >> 3, lr = lane & 7;
    const int am  = wm * 32 + lr + ((grp & 1) << 3);  // + mt*16 -> m (pixel idx)
    const int bn  = wn * 64 + lr + ((grp >> 1) << 3); // + bt*16
    const int akv = grp >> 1;                         // + 2*ks
    const int bkv = grp & 1;
    const int prow = wm >> 1;        // buffer row of this warp's pixels (0 or 1)
    int pcol[2];                     // (m&63)+1, per mt (warp-lane constant)
    #pragma unroll
    for (int mt = 0; mt < 2; mt++)
        pcol[mt] = ((am + mt * 16) & 63) + 1;

    #pragma unroll
    for (int c = 0; c < 9; c++) {
        const int s = c % 3;
        if (c < 8) asm volatile("cp.async.wait_group 1;" ::: "memory");
        else       asm volatile("cp.async.wait_group 0;" ::: "memory");
        __syncthreads();            // B stage s ready; A fill visible (c==0)

        if (c + 2 < 9) {            // refill B stage consumed at iter c-1
            loadB(c + 2, (c + 2) % 3);
            asm volatile("cp.async.commit_group;");
        }

        // A slot row for this chunk: scalar select (dy, dx are literals)
        const int dy = c / 3 - 1, dx = c % 3 - 1;
        const int rr = prow + dy + 1;                       // 0..3
        const int rowslot = ((unsigned)(h0 - 1 + rr) < 64u) ? rr : 4;
        const u32 arow = smb + SM_AR + (rowslot * 66 + dx) * 128;

        u32 abase[2]; int asw[2];
        #pragma unroll
        for (int mt = 0; mt < 2; mt++) {
            abase[mt] = arow + pcol[mt] * 128;
            asw[mt]   = (rowslot * 66 + dx + pcol[mt]) & 7;
        }
        const u32 Bb = smb + SM_B + s * 16384;

        #pragma unroll
        for (int ks = 0; ks < 4; ks++) {       // k = 16 per step
            u32 af[2][4];
            #pragma unroll
            for (int mt = 0; mt < 2; mt++)
                ldm4(af[mt], abase[mt] + (((2 * ks + akv) ^ asw[mt]) << 4));
            u32 bf[4][4];
            #pragma unroll
            for (int bt = 0; bt < 4; bt++) {
                int n = bn + bt * 16;
                ldm4(bf[bt], Bb + n * 128 + (((2 * ks + bkv) ^ (n & 7)) << 4));
            }
            #pragma unroll
            for (int mt = 0; mt < 2; mt++)
                #pragma unroll
                for (int nt = 0; nt < 8; nt++)
                    mma16(acc[mt][nt], af[mt], &bf[nt >> 1][(nt & 1) * 2]);
        }
    }

    // ---- epilogue: per-(g,pixel) Lorentz norm + staged coalesced stores ----
    __syncthreads();                         // stage aliases A/B buffers
    float* stage = (float*)sm;               // [gg][128][65]
    float* stg = stage + wn * 8320;

    #pragma unroll
    for (int mt = 0; mt < 2; mt++) {
        #pragma unroll
        for (int rr = 0; rr < 2; rr++) {
            float ssum = 0.f;
            #pragma unroll
            for (int nt = 0; nt < 8; nt++) {
                float v0 = acc[mt][nt][rr * 2];
                float v1 = acc[mt][nt][rr * 2 + 1];
                ssum = fmaf(v0, v0, fmaf(v1, v1, ssum));
            }
            ssum += __shfl_xor_sync(0xffffffffu, ssum, 1);
            ssum += __shfl_xor_sync(0xffffffffu, ssum, 2);
            int p = wm * 32 + mt * 16 + rr * 8 + (lane >> 2);
            float* row = stg + p * 65;
            if ((lane & 3) == 0) row[0] = sqrtf(1.f + ssum);
            #pragma unroll
            for (int nt = 0; nt < 8; nt++) {
                row[1 + nt * 8 + 2 * (lane & 3)] = acc[mt][nt][rr * 2];
                row[2 + nt * 8 + 2 * (lane & 3)] = acc[mt][nt][rr * 2 + 1];
            }
        }
    }
    __syncthreads();

    #pragma unroll
    for (int gg = 0; gg < 2; gg++) {
        int g = nh * 2 + gg;
        float4* dst = (float4*)(out + ((size_t)(b * 4 + g) * 64 + h0) * 64 * 65);
        const float4* src = (const float4*)(stage + gg * 8320);
        for (int i = tid; i < 2080; i += 256) dst[i] = src[i];
    }
}

extern "C" void kernel_launch(void* const* d_in, const int* in_sizes, int n_in,
                              void* d_out, int out_size) {
    const float* x   = (const float*)d_in[0];  // (16,64,64,65)
    const float* ws  = (const float*)d_in[1];  // (64,64,1,3,3)
    // d_in[2] = w_time_output : dead (its output row is replaced by the norm)
    const float* wti = (const float*)d_in[3];  // (65,1)
    float* out = (float*)d_out;

    prep_all<<<832, 256>>>(x, ws);

    cudaFuncSetAttribute(lorentz_mma_kernel,
                         cudaFuncAttributeMaxDynamicSharedMemorySize, SMEM_BYTES);
    lorentz_mma_kernel<<<1024, 256, SMEM_BYTES>>>(x, wti, out);
}

// round 15
// speedup vs baseline: 1.1356x; 1.1356x over previous
#include <cuda_runtime.h>
#include <cuda_fp16.h>
#include <math.h>
#include <stdint.h>

// ============================================================================
// GroupLorentzConv2d, fp16 m16n8k16 tensor-core path (sm_80 PTX on B200 HMMA).
//
//   C[p, n] = sum_d A[p,d] * W[n,d] + t(p)*wti[(n&63)+1],  n = g*64 + o
//   Flat-index pairing (as the reference einsum):
//     A side: d = kp*64 + cp  -> x[b, h+dy(kp), w+dx(kp), 1+cp]
//     W side: d = cw*9  + kw  -> rot90^g(weight_space[o, cw])[kw]
//   K = 576 = 9 chunks x 64 (one 3x3 tap per chunk)
//   out[b,g,h,w,0]   = sqrt(1 + sum_o C[p, g*64+o]^2)
//   out[b,g,h,w,1+o] = C[p, g*64+o]
//
// CTA: 128 pixels x 128 outputs, 8 warps (32x64 warp tile), 2 CTAs/SM.
// A RESIDENT in smem [5 rows][66 px][64ch], filled by 8 coalesced 16B cp.async
// per thread from pre-converted fp16 g_xpad (R12-14's unaligned scalar-LDG
// storm — the L1-wavefront saturation — is gone). B: 3-stage cp.async ring.
// ============================================================================

typedef uint32_t u32;

__device__ __align__(16) __half g_xpad[16 * 64 * 64 * 64]; // (b,h,w,c) c-fast
__device__ __align__(16) __half g_Wt[9 * 256 * 64];        // [tap][n][cp]
__device__ float g_tmap[16 * 64 * 64];

// ---------------- prep kernel ------------------------------------------------
// blocks [0,2048): xpad | [2048,2304): tmap | [2304,2880): weights
__global__ void prep_all(const float* __restrict__ x,
                         const float* __restrict__ ws) {
    int blk = blockIdx.x;
    if (blk < 2048) {
        int i = blk * 256 + threadIdx.x;     // 16B vector index, 0..524287
        int pix = i >> 3, v = i & 7;
        const float* src = x + (size_t)pix * 65 + 1 + v * 8;
        __half2 h2[4];
        #pragma unroll
        for (int j = 0; j < 4; j++)
            h2[j] = __floats2half2_rn(src[2 * j], src[2 * j + 1]);
        *(uint4*)(g_xpad + (size_t)i * 8) = *(uint4*)h2;
        return;
    }
    if (blk < 2304) {
        int i = (blk - 2048) * 256 + threadIdx.x;
        int w = i & 63, h = (i >> 6) & 63, b = i >> 12;
        float s = 0.f;
        #pragma unroll
        for (int dy = -1; dy <= 1; dy++) {
            int hh = h + dy;
            #pragma unroll
            for (int dx = -1; dx <= 1; dx++) {
                int ww = w + dx;
                float v = 0.f;
                if (hh >= 0 && hh < 64 && ww >= 0 && ww < 64)
                    v = x[((size_t)(b * 64 + hh) * 64 + ww) * 65];
                v = fmaxf(v, 1.0f);
                s = fmaf(v, v, s);
            }
        }
        g_tmap[i] = sqrtf(s - 8.0f);
        return;
    }
    {
        int i = (blk - 2304) * 256 + threadIdx.x;   // [tap][n][cp]
        if (i >= 9 * 256 * 64) return;
        int kc = i & 63;                 // cp (k within chunk)
        int n  = (i >> 6) & 255;
        int kp = i >> 14;                // tap
        int g = n >> 6, o = n & 63;
        int d  = kp * 64 + kc;           // flat index, tap-major (A side)
        int cw = d / 9, kw = d - cw * 9; // same d, channel-major (W side)
        int r = kw / 3, cc = kw - r * 3;
        int i2, j2;
        switch (g) {              // numpy rot90^g (CCW): rot90(A)[i,j] = A[j, 2-i]
            case 0:  i2 = r;      j2 = cc;     break;
            case 1:  i2 = cc;     j2 = 2 - r;  break;
            case 2:  i2 = 2 - r;  j2 = 2 - cc; break;
            default: i2 = 2 - cc; j2 = r;      break;
        }
        g_Wt[i] = __float2half_rn(ws[(o * 64 + cw) * 9 + i2 * 3 + j2]);
    }
}

// ---------------- main kernel ------------------------------------------------
// smem: A-resident [5 rows][66 px][128 B]      @0      (42,240 B)
//       B ring: 3 stages x [128 n][64 k]f16    @43008  (3 x 16,384 B)
//       stage float[2][128][65]                @0      (66,560 B, aliases, post-loop)
#define SM_AR 0
#define SM_B  43008
#define SMEM_BYTES (43008 + 49152)

__device__ __forceinline__ void cp16(u32 dst, const void* src, int sz) {
    asm volatile("cp.async.cg.shared.global [%0], [%1], 16, %2;"
                 :: "r"(dst), "l"(src), "r"(sz));
}
__device__ __forceinline__ void ldm4(u32* r, u32 addr) {
    asm volatile("ldmatrix.sync.aligned.m8n8.x4.shared.b16 {%0,%1,%2,%3}, [%4];"
                 : "=r"(r[0]), "=r"(r[1]), "=r"(r[2]), "=r"(r[3]) : "r"(addr));
}
__device__ __forceinline__ void mma16(float* c, const u32* a, const u32* b) {
    asm volatile(
        "mma.sync.aligned.m16n8k16.row.col.f32.f16.f16.f32 "
        "{%0,%1,%2,%3}, {%4,%5,%6,%7}, {%8,%9}, {%0,%1,%2,%3};"
        : "+f"(c[0]), "+f"(c[1]), "+f"(c[2]), "+f"(c[3])
        : "r"(a[0]), "r"(a[1]), "r"(a[2]), "r"(a[3]), "r"(b[0]), "r"(b[1]));
}

__global__ void __launch_bounds__(256, 2) lorentz_mma_kernel(
    const float* __restrict__ wti,   // (65,1)
    float* __restrict__ out)         // (16,4,64,64,65)
{
    extern __shared__ __align__(16) char sm[];
    const int tid  = threadIdx.x;
    const int lane = tid & 31, wid = tid >> 5;
    const int wm = wid & 3;          // pixel-warp 0..3  (32 px each)
    const int wn = wid >> 2;         // out-warp 0..1    (64 out each = one g)
    const int bid = blockIdx.x;
    const int nh  = bid & 1;         // n-half: outputs [nh*128, nh*128+128)
    const int mt_ = bid >> 1;
    const int b   = mt_ >> 5;
    const int h0  = (mt_ & 31) << 1; // rows h0, h0+1

    const u32 smb = (u32)__cvta_generic_to_shared(sm);

    // ---- B loader: 3-stage cp.async ring (XOR-swizzled) ----
    auto loadB = [&](int kp, int s) {
        const __half* base = g_Wt + ((size_t)kp * 256 + nh * 128) * 64;
        #pragma unroll
        for (int it = 0; it < 4; it++) {
            int idx = tid + it * 256;        // 128 n x 8 vec
            int n = idx >> 3, v = idx & 7;
            cp16(smb + SM_B + s * 16384 + n * 128 + ((v ^ (n & 7)) << 4),
                 base + idx * 8, 16);
        }
    };

    // ---- A-resident fill: 8 coalesced 16B cp.async per thread --------------
    // rows 0..3 = image rows h0-1..h0+2 (OOB rows zero-filled via sz=0;
    // they are also never read — rowslot redirects OOB to row 4).
    {
        #pragma unroll
        for (int it = 0; it < 8; it++) {
            int idx = tid + it * 256;        // 0..2047: 4 rows x 64 px x 8 vec
            int r  = idx >> 9;
            int px = (idx >> 3) & 63;
            int v  = idx & 7;
            int hh = h0 - 1 + r;
            bool ok = ((unsigned)hh < 64u);
            const __half* src = g_xpad +
                (((size_t)(b * 64 + (ok ? hh : 0)) * 64 + px) << 6) + v * 8;
            int slot = r * 66 + px + 1;
            cp16(smb + SM_AR + slot * 128 + ((v ^ (slot & 7)) << 4),
                 src, ok ? 16 : 0);
        }
    }
    loadB(0, 0);
    asm volatile("cp.async.commit_group;");   // group 0: A fill + B stage 0
    loadB(1, 1);
    asm volatile("cp.async.commit_group;");   // group 1: B stage 1

    // ---- border zeroing: row 4 (66 slots) + cols 0/65 of rows 0-3 ----------
    // (disjoint from cp.async-filled interior slots; visible after the c==0
    //  __syncthreads)
    {
        float4 z = make_float4(0.f, 0.f, 0.f, 0.f);
        for (int i = tid; i < 592; i += 256) {       // 74 slots x 8 float4
            int s = i >> 3, v = i & 7;
            int slot;
            if (s < 66) slot = 4 * 66 + s;
            else { int t = s - 66; slot = (t >> 1) * 66 + ((t & 1) ? 65 : 0); }
            *(float4*)(sm + SM_AR + slot * 128 + v * 16) = z;
        }
    }

    // ---- accumulator init: exact-fp32 rank-1 time term ----
    float tv[2][2];
    #pragma unroll
    for (int mt = 0; mt < 2; mt++)
        #pragma unroll
        for (int rr = 0; rr < 2; rr++) {
            int p = wm * 32 + mt * 16 + rr * 8 + (lane >> 2);
            tv[mt][rr] = g_tmap[(size_t)(b * 64 + h0 + (p >> 6)) * 64 + (p & 63)];
        }
    float acc[2][8][4];
    #pragma unroll
    for (int nt = 0; nt < 8; nt++) {
        float w0 = wti[1 + nt * 8 + 2 * (lane & 3)];
        float w1 = wti[2 + nt * 8 + 2 * (lane & 3)];
        #pragma unroll
        for (int mt = 0; mt < 2; mt++) {
            acc[mt][nt][0] = tv[mt][0] * w0;
            acc[mt][nt][1] = tv[mt][0] * w1;
            acc[mt][nt][2] = tv[mt][1] * w0;
            acc[mt][nt][3] = tv[mt][1] * w1;
        }
    }

    // ---- main loop: 9 tap-chunks (k=64), FULLY UNROLLED ---------------------
    const int grp = lane >> 3, lr = lane & 7;
    const int am  = wm * 32 + lr + ((grp & 1) << 3);  // + mt*16 -> m (pixel idx)
    const int bn  = wn * 64 + lr + ((grp >> 1) << 3); // + bt*16
    const int akv = grp >> 1;                         // + 2*ks
    const int bkv = grp & 1;
    const int prow = wm >> 1;        // buffer row of this warp's pixels (0 or 1)
    int pcol[2];                     // (m&63)+1, per mt (warp-lane constant)
    #pragma unroll
    for (int mt = 0; mt < 2; mt++)
        pcol[mt] = ((am + mt * 16) & 63) + 1;

    #pragma unroll
    for (int c = 0; c < 9; c++) {
        const int s = c % 3;
        if (c < 8) asm volatile("cp.async.wait_group 1;" ::: "memory");
        else       asm volatile("cp.async.wait_group 0;" ::: "memory");
        __syncthreads();            // B stage s ready; A fill+border visible

        if (c + 2 < 9) {            // refill B stage consumed at iter c-1
            loadB(c + 2, (c + 2) % 3);
            asm volatile("cp.async.commit_group;");
        }

        // A slot row for this chunk: scalar select (dy, dx are literals)
        const int dy = c / 3 - 1, dx = c % 3 - 1;
        const int rr = prow + dy + 1;                       // 0..3
        const int rowslot = ((unsigned)(h0 - 1 + rr) < 64u) ? rr : 4;
        const u32 arow = smb + SM_AR + (rowslot * 66 + dx) * 128;

        u32 abase[2]; int asw[2];
        #pragma unroll
        for (int mt = 0; mt < 2; mt++) {
            abase[mt] = arow + pcol[mt] * 128;
            asw[mt]   = (rowslot * 66 + dx + pcol[mt]) & 7;
        }
        const u32 Bb = smb + SM_B + s * 16384;

        #pragma unroll
        for (int ks = 0; ks < 4; ks++) {       // k = 16 per step
            u32 af[2][4];
            #pragma unroll
            for (int mt = 0; mt < 2; mt++)
                ldm4(af[mt], abase[mt] + (((2 * ks + akv) ^ asw[mt]) << 4));
            u32 bf[4][4];
            #pragma unroll
            for (int bt = 0; bt < 4; bt++) {
                int n = bn + bt * 16;
                ldm4(bf[bt], Bb + n * 128 + (((2 * ks + bkv) ^ (n & 7)) << 4));
            }
            #pragma unroll
            for (int mt = 0; mt < 2; mt++)
                #pragma unroll
                for (int nt = 0; nt < 8; nt++)
                    mma16(acc[mt][nt], af[mt], &bf[nt >> 1][(nt & 1) * 2]);
        }
    }

    // ---- epilogue: per-(g,pixel) Lorentz norm + staged coalesced stores ----
    __syncthreads();                         // stage aliases A/B buffers
    float* stage = (float*)sm;               // [gg][128][65]
    float* stg = stage + wn * 8320;

    #pragma unroll
    for (int mt = 0; mt < 2; mt++) {
        #pragma unroll
        for (int rr = 0; rr < 2; rr++) {
            float ssum = 0.f;
            #pragma unroll
            for (int nt = 0; nt < 8; nt++) {
                float v0 = acc[mt][nt][rr * 2];
                float v1 = acc[mt][nt][rr * 2 + 1];
                ssum = fmaf(v0, v0, fmaf(v1, v1, ssum));
            }
            ssum += __shfl_xor_sync(0xffffffffu, ssum, 1);
            ssum += __shfl_xor_sync(0xffffffffu, ssum, 2);
            int p = wm * 32 + mt * 16 + rr * 8 + (lane >> 2);
            float* row = stg + p * 65;
            if ((lane & 3) == 0) row[0] = sqrtf(1.f + ssum);
            #pragma unroll
            for (int nt = 0; nt < 8; nt++) {
                row[1 + nt * 8 + 2 * (lane & 3)] = acc[mt][nt][rr * 2];
                row[2 + nt * 8 + 2 * (lane & 3)] = acc[mt][nt][rr * 2 + 1];
            }
        }
    }
    __syncthreads();

    #pragma unroll
    for (int gg = 0; gg < 2; gg++) {
        int g = nh * 2 + gg;
        float4* dst = (float4*)(out + ((size_t)(b * 4 + g) * 64 + h0) * 64 * 65);
        const float4* src = (const float4*)(stage + gg * 8320);
        for (int i = tid; i < 2080; i += 256) dst[i] = src[i];
    }
}

extern "C" void kernel_launch(void* const* d_in, const int* in_sizes, int n_in,
                              void* d_out, int out_size) {
    const float* x   = (const float*)d_in[0];  // (16,64,64,65)
    const float* ws  = (const float*)d_in[1];  // (64,64,1,3,3)
    // d_in[2] = w_time_output : dead (its output row is replaced by the norm)
    const float* wti = (const float*)d_in[3];  // (65,1)
    float* out = (float*)d_out;

    prep_all<<<2880, 256>>>(x, ws);

    cudaFuncSetAttribute(lorentz_mma_kernel,
                         cudaFuncAttributeMaxDynamicSharedMemorySize, SMEM_BYTES);
    lorentz_mma_kernel<<<1024, 256, SMEM_BYTES>>>(wti, out);
}